// round 2
// baseline (speedup 1.0000x reference)
#include <cuda_runtime.h>
#include <cuda_fp16.h>
#include <cstdint>

// Problem dims (fixed by the dataset)
#define B_ 64
#define T_ 2048
#define I_ 256
#define H_ 256
#define G4_ 1024  // 4*H

// Scratch for the input projection xz = x@Wx + b : [B,T,4H] fp32 (537 MB).
__device__ float g_xz[(size_t)B_ * T_ * G4_];

// ---------------------------------------------------------------------------
// Kernel 1: xz[m][n] = sum_k x[m][k] * Wx[k][n] + b[n]
// M = B*T = 131072, K = 256, N = 1024. fp32 tiled GEMM. (unchanged from R1)
// ---------------------------------------------------------------------------
__global__ __launch_bounds__(256) void gemm_xz_kernel(
    const float* __restrict__ x, const float* __restrict__ Wx,
    const float* __restrict__ bias)
{
    const int BK = 16;
    __shared__ float As[16][130];
    __shared__ float Bs[16][128];

    const int tid = threadIdx.x;
    const int m0 = blockIdx.y * 128;
    const int n0 = blockIdx.x * 128;
    const int ty = tid >> 4;
    const int tx = tid & 15;

    float acc[8][8];
#pragma unroll
    for (int i = 0; i < 8; i++)
#pragma unroll
        for (int j = 0; j < 8; j++) acc[i][j] = 0.f;

    const int arow = tid >> 2;
    const int akq  = tid & 3;
    const int bk   = tid >> 5;
    const int bn4  = (tid & 31) << 2;

    for (int k0 = 0; k0 < 256; k0 += BK) {
#pragma unroll
        for (int h = 0; h < 2; h++) {
            int row = arow + h * 64;
            float4 v = *reinterpret_cast<const float4*>(&x[(size_t)(m0 + row) * 256 + k0 + akq * 4]);
            As[akq * 4 + 0][row] = v.x;
            As[akq * 4 + 1][row] = v.y;
            As[akq * 4 + 2][row] = v.z;
            As[akq * 4 + 3][row] = v.w;
        }
#pragma unroll
        for (int h = 0; h < 2; h++) {
            int kk = bk + h * 8;
            float4 v = *reinterpret_cast<const float4*>(&Wx[(size_t)(k0 + kk) * 1024 + n0 + bn4]);
            *reinterpret_cast<float4*>(&Bs[kk][bn4]) = v;
        }
        __syncthreads();

#pragma unroll
        for (int kk = 0; kk < BK; kk++) {
            float a[8], b[8];
#pragma unroll
            for (int i = 0; i < 8; i++) a[i] = As[kk][ty + 16 * i];
#pragma unroll
            for (int j = 0; j < 8; j++) b[j] = Bs[kk][tx + 16 * j];
#pragma unroll
            for (int i = 0; i < 8; i++)
#pragma unroll
                for (int j = 0; j < 8; j++)
                    acc[i][j] = fmaf(a[i], b[j], acc[i][j]);
        }
        __syncthreads();
    }

#pragma unroll
    for (int i = 0; i < 8; i++) {
        int m = m0 + ty + 16 * i;
#pragma unroll
        for (int j = 0; j < 8; j++) {
            int n = n0 + tx + 16 * j;
            g_xz[(size_t)m * 1024 + n] = acc[i][j] + bias[n];
        }
    }
}

// ---------------------------------------------------------------------------
// Kernel 2: LSTM scan, register-resident weights + packed f32x2 FMA.
//
// 16 clusters x 8 CTAs; cluster handles 4 batches. CTA rank r owns units
// [32r, 32r+32) of every gate => 128 columns of Wh. Each of the 512 threads
// holds a 64-k slice of one column's weights in REGISTERS as 32 packed f32x2
// values (64 regs). Per step: h (SMEM, parity double-buffered, broadcast
// reads) -> 2 FFMA2 + 1 LDS.v2.u64 per 4 MACs. Partial sums reduced through
// SMEM; gates/cell update by 128 threads; h scattered to all 8 CTAs via
// DSMEM; split cluster arrive/wait per step.
// ---------------------------------------------------------------------------
__device__ __forceinline__ float sigf(float z) {
    return 1.0f / (1.0f + __expf(-z));
}

__global__ __launch_bounds__(512, 1) __cluster_dims__(8, 1, 1)
void lstm_scan_kernel(const float* __restrict__ Wh,
                      const float* __restrict__ h0,
                      const float* __restrict__ c0,
                      float* __restrict__ out)
{
    __shared__ float hbuf[2][4][256];   // [parity][batch][k]  8 KB
    __shared__ float zred[16][128];     // [ks*4+b][local col] 8 KB

    const int tid = threadIdx.x;
    unsigned rank;
    asm("mov.u32 %0, %%cluster_ctarank;" : "=r"(rank));
    const int b0 = (blockIdx.x >> 3) * 4;   // first batch of this cluster

    const int ks = tid >> 7;    // k-split 0..3 (64 k each)
    const int lc = tid & 127;   // local column 0..127
    const int g  = lc >> 5;     // gate 0..3
    const int u  = lc & 31;     // unit within CTA slice
    const int gcol = (g << 8) + ((int)rank << 5) + u;  // global column in [0,1024)

    // ---- Load this thread's weight slice into registers, packed f32x2 ----
    unsigned long long w2[32];
    {
        const int k0 = ks * 64;
#pragma unroll
        for (int j = 0; j < 32; j++) {
            unsigned long long lo = __float_as_uint(Wh[(size_t)(k0 + 2 * j    ) * 1024 + gcol]);
            unsigned long long hi = __float_as_uint(Wh[(size_t)(k0 + 2 * j + 1) * 1024 + gcol]);
            w2[j] = lo | (hi << 32);
        }
    }

    // ---- Init h buffer (parity 0): every CTA holds all 4 batches' h ----
    for (int i = tid; i < 4 * 256; i += 512) {
        int b = i >> 8, k = i & 255;
        hbuf[0][b][k] = h0[(size_t)(b0 + b) * 256 + k];
    }

    // ---- Updater role (tid < 128): (batch b_u, unit u_u) ----
    const int b_u = tid >> 5;
    const int u_u = tid & 31;
    const int gu  = ((int)rank << 5) + u_u;   // global unit 0..255
    float c_reg = 0.f;
    if (tid < 128) c_reg = c0[(size_t)(b0 + b_u) * 256 + gu];

    const unsigned hbase = (unsigned)__cvta_generic_to_shared(&hbuf[0][0][0]);

    __syncthreads();
    asm volatile("barrier.cluster.arrive.aligned;" ::: "memory");

    for (int t = 0; t < T_; t++) {
        const int p = t & 1;

        // Prefetch xz for this step (doesn't touch hbuf -> overlaps barrier)
        float xzv0 = 0.f, xzv1 = 0.f, xzv2 = 0.f, xzv3 = 0.f;
        if (tid < 128) {
            const float* xp = &g_xz[((size_t)(b0 + b_u) * T_ + t) * 1024 + gu];
            xzv0 = __ldg(xp);
            xzv1 = __ldg(xp + 256);
            xzv2 = __ldg(xp + 512);
            xzv3 = __ldg(xp + 768);
        }

        // Wait for previous step's DSMEM h-scatter (cluster-wide)
        asm volatile("barrier.cluster.wait.aligned;" ::: "memory");

        // ---- Dot: 4 batches x 64 k, weights in registers ----
        const unsigned hpb = hbase + (unsigned)(p * 4096 + ks * 256);
#pragma unroll
        for (int b = 0; b < 4; b++) {
            const unsigned addr = hpb + (unsigned)(b * 1024);
            unsigned long long acc0 = 0ull, acc1 = 0ull;
#pragma unroll
            for (int j = 0; j < 16; j++) {
                unsigned long long h01, h23;
                asm volatile("ld.shared.v2.u64 {%0,%1}, [%2];"
                             : "=l"(h01), "=l"(h23) : "r"(addr + (unsigned)(j * 16)));
                asm volatile("fma.rn.f32x2 %0, %1, %2, %0;"
                             : "+l"(acc0) : "l"(w2[2 * j]), "l"(h01));
                asm volatile("fma.rn.f32x2 %0, %1, %2, %0;"
                             : "+l"(acc1) : "l"(w2[2 * j + 1]), "l"(h23));
            }
            float a_lo = __uint_as_float((unsigned)acc0);
            float a_hi = __uint_as_float((unsigned)(acc0 >> 32));
            float b_lo = __uint_as_float((unsigned)acc1);
            float b_hi = __uint_as_float((unsigned)(acc1 >> 32));
            zred[ks * 4 + b][lc] = (a_lo + a_hi) + (b_lo + b_hi);
        }
        __syncthreads();

        // ---- Gates + cell update + h scatter (128 threads) ----
        if (tid < 128) {
            float zi = xzv0, zf = xzv1, zg = xzv2, zo = xzv3;
#pragma unroll
            for (int s = 0; s < 4; s++) {
                zi += zred[s * 4 + b_u][      u_u];
                zf += zred[s * 4 + b_u][ 32 + u_u];
                zg += zred[s * 4 + b_u][ 64 + u_u];
                zo += zred[s * 4 + b_u][ 96 + u_u];
            }
            float gi = sigf(zi);
            float gf = sigf(zf);
            float gg = 2.f * sigf(2.f * zg) - 1.f;   // tanh
            float go = sigf(zo);
            c_reg = gf * c_reg + gi * gg;
            float th = 2.f * sigf(2.f * c_reg) - 1.f;
            float h = go * th;

            out[((size_t)(b0 + b_u) * T_ + t) * 256 + gu] = h;

            // Scatter h into every cluster CTA's next-parity buffer
            const unsigned off = hbase +
                (unsigned)(((p ^ 1) * 4 + b_u) * 1024 + gu * 4);
#pragma unroll
            for (unsigned rr = 0; rr < 8; rr++) {
                unsigned ra;
                asm("mapa.shared::cluster.u32 %0, %1, %2;" : "=r"(ra) : "r"(off), "r"(rr));
                asm volatile("st.shared::cluster.f32 [%0], %1;" :: "r"(ra), "f"(h));
            }
        }
        asm volatile("barrier.cluster.arrive.aligned;" ::: "memory");
    }
    // Final pairing wait: no CTA exits while peers' DSMEM traffic is in flight
    asm volatile("barrier.cluster.wait.aligned;" ::: "memory");
}

// ---------------------------------------------------------------------------
extern "C" void kernel_launch(void* const* d_in, const int* in_sizes, int n_in,
                              void* d_out, int out_size)
{
    const float* x    = (const float*)d_in[0];
    const float* Wx   = (const float*)d_in[1];
    const float* Wh   = (const float*)d_in[2];
    const float* bias = (const float*)d_in[3];
    const float* h0   = (const float*)d_in[4];
    const float* c0   = (const float*)d_in[5];
    float* out = (float*)d_out;

    // Phase 1: input projection
    dim3 g1(1024 / 128, (B_ * T_) / 128);  // (8, 1024)
    gemm_xz_kernel<<<g1, 256>>>(x, Wx, bias);

    // Phase 2: recurrent scan (16 clusters of 8 CTAs, 4 batches each)
    lstm_scan_kernel<<<128, 512>>>(Wh, h0, c0, out);
}

// round 3
// speedup vs baseline: 1.5540x; 1.5540x over previous
#include <cuda_runtime.h>
#include <cstdint>

// Problem dims (fixed by the dataset)
#define B_ 64
#define T_ 2048
#define I_ 256
#define H_ 256
#define G4_ 1024  // 4*H

// Scratch for the input projection xz = x@Wx + b : [B,T,4H] fp32 (537 MB).
__device__ float g_xz[(size_t)B_ * T_ * G4_];

// ---------------------------------------------------------------------------
// Kernel 1: xz[m][n] = sum_k x[m][k] * Wx[k][n] + b[n]
// M = 131072, K = 256, N = 1024. fp32 tiled GEMM with packed f32x2 FMA.
// BM=128, BN=128, BK=16, 256 threads; each thread: 8 rows x 4 col-pairs.
// ---------------------------------------------------------------------------
__global__ __launch_bounds__(256) void gemm_xz_kernel(
    const float* __restrict__ x, const float* __restrict__ Wx,
    const float* __restrict__ bias)
{
    const int BK = 16;
    __shared__ float As[16][130];
    __shared__ float Bs[16][128];

    const int tid = threadIdx.x;
    const int m0 = blockIdx.y * 128;
    const int n0 = blockIdx.x * 128;
    const int ty = tid >> 4;   // 0..15 (row group)
    const int tx = tid & 15;   // 0..15 (col-pair group)

    unsigned long long acc2[8][4];
#pragma unroll
    for (int i = 0; i < 8; i++)
#pragma unroll
        for (int j = 0; j < 4; j++) acc2[i][j] = 0ull;

    const int arow = tid >> 2;
    const int akq  = tid & 3;
    const int bk   = tid >> 5;
    const int bn4  = (tid & 31) << 2;

    for (int k0 = 0; k0 < 256; k0 += BK) {
#pragma unroll
        for (int h = 0; h < 2; h++) {
            int row = arow + h * 64;
            float4 v = *reinterpret_cast<const float4*>(&x[(size_t)(m0 + row) * 256 + k0 + akq * 4]);
            As[akq * 4 + 0][row] = v.x;
            As[akq * 4 + 1][row] = v.y;
            As[akq * 4 + 2][row] = v.z;
            As[akq * 4 + 3][row] = v.w;
        }
#pragma unroll
        for (int h = 0; h < 2; h++) {
            int kk = bk + h * 8;
            float4 v = *reinterpret_cast<const float4*>(&Wx[(size_t)(k0 + kk) * 1024 + n0 + bn4]);
            *reinterpret_cast<float4*>(&Bs[kk][bn4]) = v;
        }
        __syncthreads();

#pragma unroll
        for (int kk = 0; kk < BK; kk++) {
            float a_[8];
            unsigned long long b2[4];
#pragma unroll
            for (int i = 0; i < 8; i++) a_[i] = As[kk][ty + 16 * i];
#pragma unroll
            for (int j = 0; j < 4; j++)
                b2[j] = *reinterpret_cast<const unsigned long long*>(&Bs[kk][32 * j + 2 * tx]);
#pragma unroll
            for (int i = 0; i < 8; i++) {
                unsigned long long a2;
                asm("mov.b64 %0, {%1, %1};" : "=l"(a2) : "f"(a_[i]));
#pragma unroll
                for (int j = 0; j < 4; j++)
                    asm("fma.rn.f32x2 %0, %1, %2, %0;" : "+l"(acc2[i][j]) : "l"(a2), "l"(b2[j]));
            }
        }
        __syncthreads();
    }

#pragma unroll
    for (int i = 0; i < 8; i++) {
        int m = m0 + ty + 16 * i;
#pragma unroll
        for (int j = 0; j < 4; j++) {
            int n = n0 + 32 * j + 2 * tx;
            float lo = __uint_as_float((unsigned)acc2[i][j]);
            float hi = __uint_as_float((unsigned)(acc2[i][j] >> 32));
            float2 o;
            o.x = lo + __ldg(&bias[n]);
            o.y = hi + __ldg(&bias[n + 1]);
            *reinterpret_cast<float2*>(&g_xz[(size_t)m * 1024 + n]) = o;
        }
    }
}

// ---------------------------------------------------------------------------
// Kernel 2: LSTM scan. 32 clusters x 4 CTAs; cluster = 2 batches.
// CTA rank r owns cols {g*256 + r*64 + u : g<4, u<64} (256 cols of Wh).
// All-fp32. Weights: half register-resident (f32x2), half SMEM (f32x2).
// 512 threads = 2 k-splits x 256 cols. Inner loop: LDS.128 broadcast of h
// pairs + packed fma.rn.f32x2. Partials via SMEM; 128 updater threads do
// gates + DSMEM h-scatter; one 4-CTA cluster barrier per step.
// ---------------------------------------------------------------------------
__device__ __forceinline__ float sigf(float z) {
    return 1.0f / (1.0f + __expf(-z));
}

__global__ __launch_bounds__(512, 1) __cluster_dims__(4, 1, 1)
void lstm_scan_kernel(const float* __restrict__ Wh,
                      const float* __restrict__ h0,
                      const float* __restrict__ c0,
                      float* __restrict__ out)
{
    extern __shared__ unsigned long long ws[];  // [64][256] f32x2 = 128 KB
    __shared__ float4 hbuf[2][128];             // [parity][j] {b0[2j],b0[2j+1],b1[2j],b1[2j+1]}
    __shared__ float zred[2][2][256];           // [ksplit][batch][lc]

    const int tid = threadIdx.x;
    unsigned rank;
    asm("mov.u32 %0, %%cluster_ctarank;" : "=r"(rank));
    const int b0 = (blockIdx.x >> 2) * 2;

    const int ks = tid >> 8;      // 0..1  (k-half)
    const int lc = tid & 255;     // local column
    const int g  = lc >> 6;       // gate
    const int u  = lc & 63;       // unit within CTA slice
    const int gcol = (g << 8) + ((int)rank << 6) + u;   // global col in [0,1024)

    // ---- Weight residency: 32 k-pairs in regs, 32 k-pairs in SMEM ----
    unsigned long long wreg[32];
    {
        const int kb = ks * 128;
#pragma unroll
        for (int jj = 0; jj < 32; jj++) {
            unsigned long long lo = __float_as_uint(Wh[(size_t)(kb + 2 * jj    ) * 1024 + gcol]);
            unsigned long long hi = __float_as_uint(Wh[(size_t)(kb + 2 * jj + 1) * 1024 + gcol]);
            wreg[jj] = lo | (hi << 32);
        }
        const int kb2 = ks * 128 + 64;
        for (int jj = 0; jj < 32; jj++) {
            unsigned long long lo = __float_as_uint(Wh[(size_t)(kb2 + 2 * jj    ) * 1024 + gcol]);
            unsigned long long hi = __float_as_uint(Wh[(size_t)(kb2 + 2 * jj + 1) * 1024 + gcol]);
            ws[(ks * 32 + jj) * 256 + lc] = lo | (hi << 32);
        }
    }

    // ---- Init h buffer (parity 0) ----
    if (tid < 128) {
        int j = tid;
        float4 v;
        v.x = h0[(size_t)(b0    ) * 256 + 2 * j    ];
        v.y = h0[(size_t)(b0    ) * 256 + 2 * j + 1];
        v.z = h0[(size_t)(b0 + 1) * 256 + 2 * j    ];
        v.w = h0[(size_t)(b0 + 1) * 256 + 2 * j + 1];
        hbuf[0][j] = v;
    }

    // ---- Updater role (tid < 128): (batch b_u, unit u_u) ----
    const int b_u = tid >> 6;
    const int u_u = tid & 63;
    const int gu  = ((int)rank << 6) + u_u;
    float c_reg = 0.f;
    if (tid < 128) c_reg = c0[(size_t)(b0 + b_u) * 256 + gu];

    const unsigned hbase = (unsigned)__cvta_generic_to_shared(&hbuf[0][0]);
    const unsigned wbase = (unsigned)__cvta_generic_to_shared(ws);

    __syncthreads();
    asm volatile("barrier.cluster.arrive.aligned;" ::: "memory");

    for (int t = 0; t < T_; t++) {
        const int p = t & 1;

        // Prefetch xz for this step (overlaps cluster barrier latency)
        float xzv0 = 0.f, xzv1 = 0.f, xzv2 = 0.f, xzv3 = 0.f;
        if (tid < 128) {
            const float* xp = &g_xz[((size_t)(b0 + b_u) * T_ + t) * 1024 + gu];
            xzv0 = __ldg(xp);
            xzv1 = __ldg(xp + 256);
            xzv2 = __ldg(xp + 512);
            xzv3 = __ldg(xp + 768);
        }

        // Wait for previous step's h-scatter
        asm volatile("barrier.cluster.wait.aligned;" ::: "memory");

        const unsigned haddr = hbase + (unsigned)(p * 2048 + ks * 1024);
        unsigned long long a00 = 0ull, a01 = 0ull, a10 = 0ull, a11 = 0ull;

        // Reg-weight half: 32 k-pairs
#pragma unroll
        for (int jj = 0; jj < 32; jj += 2) {
            unsigned long long h0a, h1a, h0b, h1b;
            asm volatile("ld.shared.v2.u64 {%0,%1}, [%2];"
                         : "=l"(h0a), "=l"(h1a) : "r"(haddr + (unsigned)(jj * 16)));
            asm volatile("ld.shared.v2.u64 {%0,%1}, [%2];"
                         : "=l"(h0b), "=l"(h1b) : "r"(haddr + (unsigned)(jj * 16 + 16)));
            asm volatile("fma.rn.f32x2 %0, %1, %2, %0;" : "+l"(a00) : "l"(wreg[jj]),     "l"(h0a));
            asm volatile("fma.rn.f32x2 %0, %1, %2, %0;" : "+l"(a10) : "l"(wreg[jj]),     "l"(h1a));
            asm volatile("fma.rn.f32x2 %0, %1, %2, %0;" : "+l"(a01) : "l"(wreg[jj + 1]), "l"(h0b));
            asm volatile("fma.rn.f32x2 %0, %1, %2, %0;" : "+l"(a11) : "l"(wreg[jj + 1]), "l"(h1b));
        }
        // SMEM-weight half: 32 k-pairs
        const unsigned waddr = wbase + (unsigned)((ks * 32 * 256 + lc) * 8);
#pragma unroll
        for (int jj = 0; jj < 32; jj += 2) {
            unsigned long long wa, wb, h0a, h1a, h0b, h1b;
            asm volatile("ld.shared.u64 %0, [%1];"
                         : "=l"(wa) : "r"(waddr + (unsigned)(jj * 2048)));
            asm volatile("ld.shared.u64 %0, [%1];"
                         : "=l"(wb) : "r"(waddr + (unsigned)(jj * 2048 + 2048)));
            asm volatile("ld.shared.v2.u64 {%0,%1}, [%2];"
                         : "=l"(h0a), "=l"(h1a) : "r"(haddr + (unsigned)(512 + jj * 16)));
            asm volatile("ld.shared.v2.u64 {%0,%1}, [%2];"
                         : "=l"(h0b), "=l"(h1b) : "r"(haddr + (unsigned)(512 + jj * 16 + 16)));
            asm volatile("fma.rn.f32x2 %0, %1, %2, %0;" : "+l"(a00) : "l"(wa), "l"(h0a));
            asm volatile("fma.rn.f32x2 %0, %1, %2, %0;" : "+l"(a10) : "l"(wa), "l"(h1a));
            asm volatile("fma.rn.f32x2 %0, %1, %2, %0;" : "+l"(a01) : "l"(wb), "l"(h0b));
            asm volatile("fma.rn.f32x2 %0, %1, %2, %0;" : "+l"(a11) : "l"(wb), "l"(h1b));
        }

        {
            float s0 = __uint_as_float((unsigned)a00) + __uint_as_float((unsigned)(a00 >> 32))
                     + __uint_as_float((unsigned)a01) + __uint_as_float((unsigned)(a01 >> 32));
            float s1 = __uint_as_float((unsigned)a10) + __uint_as_float((unsigned)(a10 >> 32))
                     + __uint_as_float((unsigned)a11) + __uint_as_float((unsigned)(a11 >> 32));
            zred[ks][0][lc] = s0;
            zred[ks][1][lc] = s1;
        }
        __syncthreads();

        if (tid < 128) {
            float zi = xzv0 + zred[0][b_u][      u_u] + zred[1][b_u][      u_u];
            float zf = xzv1 + zred[0][b_u][ 64 + u_u] + zred[1][b_u][ 64 + u_u];
            float zg = xzv2 + zred[0][b_u][128 + u_u] + zred[1][b_u][128 + u_u];
            float zo = xzv3 + zred[0][b_u][192 + u_u] + zred[1][b_u][192 + u_u];
            float gi = sigf(zi);
            float gf = sigf(zf);
            float gg = 2.f * sigf(2.f * zg) - 1.f;   // tanh
            float go = sigf(zo);
            c_reg = gf * c_reg + gi * gg;
            float th = 2.f * sigf(2.f * c_reg) - 1.f;
            float h = go * th;

            out[((size_t)(b0 + b_u) * T_ + t) * 256 + gu] = h;

            // Scatter h into all 4 cluster CTAs' next-parity buffer
            const unsigned off = hbase +
                (unsigned)((((p ^ 1) * 128 + (gu >> 1)) << 4) + ((2 * b_u + (gu & 1)) << 2));
#pragma unroll
            for (unsigned rr = 0; rr < 4; rr++) {
                unsigned ra;
                asm("mapa.shared::cluster.u32 %0, %1, %2;" : "=r"(ra) : "r"(off), "r"(rr));
                asm volatile("st.shared::cluster.f32 [%0], %1;" :: "r"(ra), "f"(h));
            }
        }
        asm volatile("barrier.cluster.arrive.aligned;" ::: "memory");
    }
    asm volatile("barrier.cluster.wait.aligned;" ::: "memory");
}

// ---------------------------------------------------------------------------
extern "C" void kernel_launch(void* const* d_in, const int* in_sizes, int n_in,
                              void* d_out, int out_size)
{
    const float* x    = (const float*)d_in[0];
    const float* Wx   = (const float*)d_in[1];
    const float* Wh   = (const float*)d_in[2];
    const float* bias = (const float*)d_in[3];
    const float* h0   = (const float*)d_in[4];
    const float* c0   = (const float*)d_in[5];
    float* out = (float*)d_out;

    // Phase 1: input projection
    dim3 g1(1024 / 128, (B_ * T_) / 128);  // (8, 1024)
    gemm_xz_kernel<<<g1, 256>>>(x, Wx, bias);

    // Phase 2: recurrent scan (32 clusters of 4 CTAs, 2 batches each)
    const int smem_bytes = 64 * 256 * 8;  // 131072
    cudaFuncSetAttribute(lstm_scan_kernel,
                         cudaFuncAttributeMaxDynamicSharedMemorySize, smem_bytes);
    lstm_scan_kernel<<<128, 512, smem_bytes>>>(Wh, h0, c0, out);
}